// round 6
// baseline (speedup 1.0000x reference)
#include <cuda_runtime.h>
#include <cuda_bf16.h>
#include <math.h>
#include <cstdint>

// Problem constants (fixed shapes)
#define Bb 2
#define Tt 4096
#define Dd 2048
#define Hh 16
#define Kk 128
#define Vv 128
#define BT 64
#define NT 64
#define TOKS (Bb*Tt)          // 8192
#define HD   (Hh*Kk)          // 2048
#define VS   32               // v-slice width in scan
#define NVS  (Vv/VS)          // 4

// ---------------- scratch (device globals; no runtime alloc) ----------------
__device__ float g_q [TOKS*HD];
__device__ float g_k [TOKS*HD];
__device__ float g_v [TOKS*HD];
__device__ float g_g [TOKS*HD];
__device__ float g_z [TOKS*HD];
__device__ float g_eta  [TOKS*Hh];
__device__ float g_theta[TOKS*Hh];
__device__ float g_lec  [32*Tt];
__device__ float g_elec [32*Tt];
__device__ float g_coef [32*Tt];
__device__ float g_M    [32*NT*BT*BT];
__device__ __nv_bfloat16 g_xhi[TOKS*Dd];
__device__ __nv_bfloat16 g_xlo[TOKS*Dd];
__device__ __nv_bfloat16 g_whi[5*Dd*Dd];
__device__ __nv_bfloat16 g_wlo[5*Dd*Dd];
__device__ __nv_bfloat16 g_oghi[TOKS*HD];
__device__ __nv_bfloat16 g_oglo[TOKS*HD];

// ---------------- helpers ----------------
typedef unsigned long long u64t;

__device__ __forceinline__ uint32_t smem_u32(const void* p) {
    uint32_t a;
    asm("{ .reg .u64 t; cvta.to.shared.u64 t, %1; cvt.u32.u64 %0, t; }" : "=r"(a) : "l"(p));
    return a;
}
__device__ __forceinline__ void ldm_x4(uint32_t (&r)[4], uint32_t addr) {
    asm volatile("ldmatrix.sync.aligned.m8n8.x4.shared.b16 {%0,%1,%2,%3}, [%4];"
                 : "=r"(r[0]), "=r"(r[1]), "=r"(r[2]), "=r"(r[3]) : "r"(addr));
}
__device__ __forceinline__ void mma16816(float (&d)[4], const uint32_t (&a)[4],
                                         uint32_t b0, uint32_t b1) {
    asm volatile(
        "mma.sync.aligned.m16n8k16.row.col.f32.bf16.bf16.f32 "
        "{%0,%1,%2,%3}, {%4,%5,%6,%7}, {%8,%9}, {%0,%1,%2,%3};"
        : "+f"(d[0]), "+f"(d[1]), "+f"(d[2]), "+f"(d[3])
        : "r"(a[0]), "r"(a[1]), "r"(a[2]), "r"(a[3]), "r"(b0), "r"(b1));
}
// packed f32x2 (FFMA2 path)
__device__ __forceinline__ u64t pk2(float lo, float hi) {
    u64t d; asm("mov.b64 %0, {%1,%2};" : "=l"(d) : "f"(lo), "f"(hi)); return d;
}
__device__ __forceinline__ void upk2(u64t s, float& lo, float& hi) {
    asm("mov.b64 {%0,%1}, %2;" : "=f"(lo), "=f"(hi) : "l"(s));
}
__device__ __forceinline__ u64t fma2(u64t a, u64t b, u64t c) {
    u64t d; asm("fma.rn.f32x2 %0, %1, %2, %3;" : "=l"(d) : "l"(a), "l"(b), "l"(c)); return d;
}
__device__ __forceinline__ u64t mul2(u64t a, u64t b) {
    u64t d; asm("mul.rn.f32x2 %0, %1, %2;" : "=l"(d) : "l"(a), "l"(b)); return d;
}
__device__ __forceinline__ u64t d2u(double x) { return __double_as_longlong(x); }
__device__ __forceinline__ double u2d(u64t x) { return __longlong_as_double(x); }

// ---------------- fp32 -> (hi,lo) bf16 split ----------------
__global__ __launch_bounds__(256)
void split_bf16_kernel(const float* __restrict__ x, __nv_bfloat16* __restrict__ hi,
                       __nv_bfloat16* __restrict__ lo, int n4)
{
    int i = blockIdx.x * 256 + threadIdx.x;
    if (i >= n4) return;
    float4 v = ((const float4*)x)[i];
    float vv[4] = {v.x, v.y, v.z, v.w};
    __align__(8) __nv_bfloat16 h[4], l[4];
#pragma unroll
    for (int j = 0; j < 4; j++) {
        h[j] = __float2bfloat16(vv[j]);
        l[j] = __float2bfloat16(vv[j] - __bfloat162float(h[j]));
    }
    ((uint2*)hi)[i] = *(uint2*)h;
    ((uint2*)lo)[i] = *(uint2*)l;
}

// ---------------- HMMA 3xBF16 GEMM: C[8192,2048] = alpha * A @ B^T ----------------
// CTA tile 128x256, BK=32, 5-stage cp.async pipeline, 8 warps (2M x 4N), warp 64x64.
#define BKT 32
#define NKT 192                 // 3 * (2048/32)
#define ROWB 80                 // smem row stride (32 bf16 + 8 pad)
#define STG_BYTES ((128+256)*ROWB)   // 30720
#define NSTG 5

__device__ __forceinline__ void ld_stage(uint32_t sA, uint32_t sB,
    const __nv_bfloat16* __restrict__ A, const __nv_bfloat16* __restrict__ B,
    int bm, int bn, int k0, int tid)
{
#pragma unroll
    for (int i = 0; i < 2; i++) {                 // A: 128 rows x 4 x 16B = 512
        int idx = tid + i * 256;
        int row = idx >> 2, c = idx & 3;
        uint32_t dA = sA + row * ROWB + c * 16;
        const void* pA = A + (size_t)(bm + row) * 2048 + k0 + c * 8;
        asm volatile("cp.async.cg.shared.global [%0], [%1], 16;" :: "r"(dA), "l"(pA) : "memory");
    }
#pragma unroll
    for (int i = 0; i < 4; i++) {                 // B: 256 rows x 4 x 16B = 1024
        int idx = tid + i * 256;
        int row = idx >> 2, c = idx & 3;
        uint32_t dB = sB + row * ROWB + c * 16;
        const void* pB = B + (size_t)(bn + row) * 2048 + k0 + c * 8;
        asm volatile("cp.async.cg.shared.global [%0], [%1], 16;" :: "r"(dB), "l"(pB) : "memory");
    }
}

__global__ __launch_bounds__(256, 1)
void gemm3_bf16(const __nv_bfloat16* __restrict__ Ahi, const __nv_bfloat16* __restrict__ Alo,
                const __nv_bfloat16* __restrict__ Bhi, const __nv_bfloat16* __restrict__ Blo,
                float* __restrict__ C, float alpha)
{
    extern __shared__ __align__(128) char dyn[];
    const int tid  = threadIdx.x;
    const int wid  = tid >> 5;
    const int lane = tid & 31;
    const int bm = blockIdx.y * 128;
    const int bn = blockIdx.x * 256;
    const uint32_t dynb = smem_u32(dyn);

    const int wm0 = (wid >> 2) * 64;        // 2 warps in M
    const int wn0 = (wid & 3) * 64;         // 4 warps in N

    const int q = lane >> 3, l8 = lane & 7;
    const uint32_t aoff = (uint32_t)((l8 + (q & 1) * 8) * ROWB + (q >> 1) * 16);
    const uint32_t boff = (uint32_t)((l8 + (q >> 1) * 8) * ROWB + (q & 1) * 16);

    float acc[4][8][4];
#pragma unroll
    for (int mf = 0; mf < 4; mf++)
#pragma unroll
        for (int nf = 0; nf < 8; nf++)
#pragma unroll
            for (int j = 0; j < 4; j++) acc[mf][nf][j] = 0.f;

    // prologue: stages 0..3 (all in segment 0: Ahi, Bhi)
#pragma unroll
    for (int s = 0; s < 4; s++) {
        uint32_t base = dynb + s * STG_BYTES;
        ld_stage(base, base + 128 * ROWB, Ahi, Bhi, bm, bn, s * BKT, tid);
        asm volatile("cp.async.commit_group;" ::: "memory");
    }

    for (int kt = 0; kt < NKT; kt++) {
        asm volatile("cp.async.wait_group 3;" ::: "memory");
        __syncthreads();   // all warps done with compute(kt-1); stage kt resident

        {
            int ktn = kt + 4;
            if (ktn < NKT) {
                int seg = ktn >> 6;
                int k0  = (ktn & 63) * BKT;
                const __nv_bfloat16* As_ = (seg < 2) ? Ahi : Alo;
                const __nv_bfloat16* Bs_ = (seg == 1) ? Blo : Bhi;
                uint32_t base = dynb + (ktn % NSTG) * STG_BYTES;
                ld_stage(base, base + 128 * ROWB, As_, Bs_, bm, bn, k0, tid);
            }
            asm volatile("cp.async.commit_group;" ::: "memory");
        }

        const uint32_t sA = dynb + (kt % NSTG) * STG_BYTES;
        const uint32_t sB = sA + 128 * ROWB;
#pragma unroll
        for (int ks = 0; ks < 2; ks++) {
            uint32_t a[4][4];
#pragma unroll
            for (int mf = 0; mf < 4; mf++)
                ldm_x4(a[mf], sA + (uint32_t)(wm0 + mf * 16) * ROWB + ks * 32 + aoff);
            uint32_t b[4][4];
#pragma unroll
            for (int p = 0; p < 4; p++)
                ldm_x4(b[p], sB + (uint32_t)(wn0 + p * 16) * ROWB + ks * 32 + boff);
#pragma unroll
            for (int mf = 0; mf < 4; mf++)
#pragma unroll
                for (int p = 0; p < 4; p++) {
                    mma16816(acc[mf][2*p],   a[mf], b[p][0], b[p][1]);
                    mma16816(acc[mf][2*p+1], a[mf], b[p][2], b[p][3]);
                }
        }
    }

    const int r0 = lane >> 2, c0 = (lane & 3) * 2;
#pragma unroll
    for (int mf = 0; mf < 4; mf++) {
        int rowa = bm + wm0 + mf * 16 + r0;
#pragma unroll
        for (int nf = 0; nf < 8; nf++) {
            int col = bn + wn0 + nf * 8 + c0;
            float2 v0 = {alpha * acc[mf][nf][0], alpha * acc[mf][nf][1]};
            float2 v1 = {alpha * acc[mf][nf][2], alpha * acc[mf][nf][3]};
            *(float2*)(C + (size_t)rowa * 2048 + col)       = v0;
            *(float2*)(C + (size_t)(rowa + 8) * 2048 + col) = v1;
        }
    }
}

// ---------------- eta / theta: sigmoid projections (N=16 each) ----------------
__global__ __launch_bounds__(256)
void eta_theta_kernel(const float* __restrict__ X, const float* __restrict__ Weta,
                      const float* __restrict__ Wth, float* __restrict__ Eta,
                      float* __restrict__ Th)
{
    __shared__ float sx[Dd];
    const int tok = blockIdx.x, tid = threadIdx.x;
    for (int i = tid; i < Dd/4; i += 256)
        *(float4*)&sx[i*4] = *(const float4*)(X + (size_t)tok*Dd + i*4);
    __syncthreads();
    const int p  = tid >> 3;
    const int l8 = tid & 7;
    const int h = p & 15, which = p >> 4;
    const float* w = (which ? Wth : Weta) + (size_t)h * Dd;
    float s = 0.f;
    for (int i = l8*4; i < Dd; i += 32) {
        float4 xv = *(float4*)&sx[i];
        float4 wv = *(const float4*)(w + i);
        s += xv.x*wv.x + xv.y*wv.y + xv.z*wv.z + xv.w*wv.w;
    }
    s += __shfl_xor_sync(0xffffffffu, s, 4);
    s += __shfl_xor_sync(0xffffffffu, s, 2);
    s += __shfl_xor_sync(0xffffffffu, s, 1);
    if (l8 == 0) {
        float sig = 1.f / (1.f + expf(-s));
        if (which) Th[(size_t)tok*Hh + h] = 0.1f * sig;
        else       Eta[(size_t)tok*Hh + h] = sig;
    }
}

// ---------------- decay prep ----------------
__global__ __launch_bounds__(256)
void decay_prep_kernel(const float* __restrict__ Eta, const float* __restrict__ Th,
                       float* __restrict__ Lec, float* __restrict__ Elec,
                       float* __restrict__ Coef)
{
    const int wc   = blockIdx.x * 8 + (threadIdx.x >> 5);   // bh*64+ct
    const int lane = threadIdx.x & 31;
    const int bh = wc >> 6, ct = wc & 63;
    const int b = bh >> 4, h = bh & 15;
    const size_t tokbase = (size_t)b * Tt;
    const int t = ct * BT + lane * 2;
    float e0  = Eta[(tokbase + t) * Hh + h];
    float e1  = Eta[(tokbase + t + 1) * Hh + h];
    float th0 = Th [(tokbase + t) * Hh + h];
    float th1 = Th [(tokbase + t + 1) * Hh + h];
    float l0 = logf(fmaxf(e0, 1e-8f));
    float l1 = logf(fmaxf(e1, 1e-8f));
    float s = l0 + l1;
#pragma unroll
    for (int o = 1; o < 32; o <<= 1) {
        float n = __shfl_up_sync(0xffffffffu, s, o);
        if (lane >= o) s += n;
    }
    float lec1 = s;
    float lec0 = s - l1;
    float ltot = __shfl_sync(0xffffffffu, s, 31);
    size_t base = (size_t)bh * Tt + t;
    float2 lv = {lec0, lec1};
    float2 ev = {expf(lec0), expf(lec1)};
    float2 cv = {expf(ltot - lec0) * th0, expf(ltot - lec1) * th1};
    *(float2*)(Lec  + base) = lv;
    *(float2*)(Elec + base) = ev;
    *(float2*)(Coef + base) = cv;
}

// ---------------- qkm: M[i][j] = (q_i.k_j)*beta(i,j)*theta_j, row-major (no transpose) ----------------
#define KST 130   // sK row stride (floats); 130 mod 32 = 2 -> 2-way worst case
__global__ __launch_bounds__(256)
void qkm_kernel(const float* __restrict__ Q, const float* __restrict__ Kc,
                const float* __restrict__ Lec, const float* __restrict__ Th,
                float* __restrict__ Mout)
{
    extern __shared__ float qsm[];
    float* sQ   = qsm;            // 64*132
    float* sK   = sQ + 64*132;    // 64*130
    float* sLec = sK + 64*KST;    // 64
    float* sTh  = sLec + 64;      // 64

    const int blk = blockIdx.x;   // bh*64+ct
    const int bh = blk >> 6, ct = blk & 63;
    const int b = bh >> 4, h = bh & 15;
    const int tid = threadIdx.x;
    const size_t tokbase = (size_t)b * Tt;
    const int t0 = ct * BT;
    const float* Qp = Q  + tokbase*HD + (size_t)h*Kk;
    const float* Kp = Kc + tokbase*HD + (size_t)h*Kk;

#pragma unroll
    for (int i = 0; i < 8; i++) {
        int idx = tid + i*256;
        int r = idx >> 5, c = (idx & 31) << 2;
        float4 qv = *(const float4*)(Qp + (size_t)(t0+r)*HD + c);
        *(float4*)&sQ[r*132 + c] = qv;
        float4 kv = *(const float4*)(Kp + (size_t)(t0+r)*HD + c);
        float2 k01 = {kv.x, kv.y}, k23 = {kv.z, kv.w};
        *(float2*)&sK[r*KST + c]     = k01;
        *(float2*)&sK[r*KST + c + 2] = k23;
    }
    if (tid < 64) {
        sLec[tid] = Lec[(size_t)bh * Tt + t0 + tid];
        sTh[tid]  = Th[(tokbase + t0 + tid) * Hh + h];
    }
    __syncthreads();

    const int tx = tid & 15, ty = tid >> 4;
    const int i0 = ty*4;                     // 4 consecutive i rows
    float acc[4][4];                         // [i][s], j = tx + 16*s
#pragma unroll
    for (int i = 0; i < 4; i++)
#pragma unroll
        for (int s = 0; s < 4; s++) acc[i][s] = 0.f;
#pragma unroll 4
    for (int kk = 0; kk < Kk; kk++) {
        float kj[4], qi[4];
#pragma unroll
        for (int s = 0; s < 4; s++) kj[s] = sK[(tx + 16*s)*KST + kk];
#pragma unroll
        for (int i = 0; i < 4; i++) qi[i] = sQ[(i0+i)*132 + kk];
#pragma unroll
        for (int i = 0; i < 4; i++)
#pragma unroll
            for (int s = 0; s < 4; s++) acc[i][s] += qi[i] * kj[s];
    }
    float* Mo = Mout + (size_t)blk * (BT*BT);
#pragma unroll
    for (int i = 0; i < 4; i++) {
        int ii = i0 + i;
        float li = sLec[ii];
#pragma unroll
        for (int s = 0; s < 4; s++) {
            int jj = tx + 16*s;
            float m = 0.f;
            if (jj <= ii)
                m = acc[i][s] * expf(fminf(li - sLec[jj], 0.f)) * sTh[jj];
            Mo[ii*64 + jj] = m;
        }
    }
}

// ---------------- chunked fast-weight scan: fused kW/qW pass, f32x2 ----------------
__global__ __launch_bounds__(256, 1)
void scan_kernel(const float* __restrict__ Q, const float* __restrict__ Kc,
                 const float* __restrict__ Vc, const float* __restrict__ Elec,
                 const float* __restrict__ Coef, const float* __restrict__ Mg,
                 float* __restrict__ Z)
{
    extern __shared__ float sm[];
    float* sWt   = sm;                    // [128][32]  W^T slice
    float* sQ    = sWt  + 128*VS;         // [64][132]
    float* sK    = sQ   + 64*132;         // [64][132]
    float* sVE   = sK   + 64*132;         // [64][32]
    float* sM    = sVE  + 64*VS;          // [64][68]
    float* sElec = sM   + 64*68;          // [64]
    float* sCoef = sElec + 64;            // [64]

    const int tid = threadIdx.x;
    const int bh  = blockIdx.x;
    const int b = bh >> 4, h = bh & 15;
    const int vs0 = blockIdx.y * VS;

    const size_t tokbase = (size_t)b * Tt;
    const float* Qp = Q  + tokbase*HD + (size_t)h*Kk;
    const float* Kp = Kc + tokbase*HD + (size_t)h*Kk;
    const float* Vp = Vc + tokbase*HD + (size_t)h*Vv + vs0;
    const float* Mp = Mg + (size_t)bh * (NT*BT*BT);
    float*       Zp = Z  + tokbase*HD + (size_t)h*Vv + vs0;

    for (int i = tid; i < 128*VS; i += 256) sWt[i] = 0.f;

    const int tx = tid & 7;               // v quad
    const int ty = tid >> 3;              // 0..31
    const int v0 = tx << 2;
    const int ta = ty*2, tb = ta + 1;     // row pair
    const int k0 = ty << 2;               // 4 k-rows for W update

    for (int ct = 0; ct < NT; ct++) {
        const int t0 = ct * BT;
        __syncthreads();

        // ---- loads ----
#pragma unroll
        for (int i = 0; i < 8; i++) {
            int idx = tid + i*256;
            int r = idx >> 5;
            int c = (idx & 31) << 2;
            *(float4*)&sQ[r*132 + c] = *(const float4*)(Qp + (size_t)(t0+r)*HD + c);
            *(float4*)&sK[r*132 + c] = *(const float4*)(Kp + (size_t)(t0+r)*HD + c);
        }
#pragma unroll
        for (int i = 0; i < 2; i++) {
            int idx = tid + i*256;
            int r = idx >> 3;
            int c = (idx & 7) << 2;
            *(float4*)&sVE[r*VS + c] = *(const float4*)(Vp + (size_t)(t0+r)*HD + c);
        }
#pragma unroll
        for (int i = 0; i < 4; i++) {
            int idx = tid + i*256;
            int r = idx >> 4;
            int c = (idx & 15) << 2;
            *(float4*)&sM[r*68 + c] = *(const float4*)(Mp + ct*(BT*BT) + r*64 + c);
        }
        if (tid < 64) {
            sElec[tid] = Elec[(size_t)bh*Tt + t0 + tid];
            sCoef[tid] = Coef[(size_t)bh*Tt + t0 + tid];
        }
        __syncthreads();

        // ---- Phase A: e = k@W^T - v  AND  zq = q@W^T (single W pass) ----
        u64t za01, za23, zb01, zb23;
        {
            float4 va = *(float4*)&sVE[ta*VS + v0];
            float4 vb = *(float4*)&sVE[tb*VS + v0];
            u64t ea01 = pk2(-va.x, -va.y), ea23 = pk2(-va.z, -va.w);
            u64t eb01 = pk2(-vb.x, -vb.y), eb23 = pk2(-vb.z, -vb.w);
            za01 = 0ull; za23 = 0ull; zb01 = 0ull; zb23 = 0ull;
#pragma unroll 4
            for (int kk = 0; kk < Kk; kk++) {
                double2 wd = *(double2*)&sWt[kk*VS + v0];
                u64t w01 = d2u(wd.x), w23 = d2u(wd.y);
                float ka = sK[ta*132 + kk];
                float kb = sK[tb*132 + kk];
                float qa = sQ[ta*132 + kk];
                float qb = sQ[tb*132 + kk];
                u64t ka2 = pk2(ka, ka), kb2 = pk2(kb, kb);
                u64t qa2 = pk2(qa, qa), qb2 = pk2(qb, qb);
                ea01 = fma2(ka2, w01, ea01);
                ea23 = fma2(ka2, w23, ea23);
                eb01 = fma2(kb2, w01, eb01);
                eb23 = fma2(kb2, w23, eb23);
                za01 = fma2(qa2, w01, za01);
                za23 = fma2(qa2, w23, za23);
                zb01 = fma2(qb2, w01, zb01);
                zb23 = fma2(qb2, w23, zb23);
            }
            *(double2*)&sVE[ta*VS + v0] = make_double2(u2d(ea01), u2d(ea23));
            *(double2*)&sVE[tb*VS + v0] = make_double2(u2d(eb01), u2d(eb23));
        }
        __syncthreads();

        // ---- Phase B: z = elec*zq - M@e ; Phase C accum ----
        u64t ca01[4], ca23[4];
        {
            float ea = sElec[ta], eb = sElec[tb];
            u64t ea2 = pk2(ea, ea), eb2 = pk2(eb, eb);
            za01 = mul2(za01, ea2); za23 = mul2(za23, ea2);
            zb01 = mul2(zb01, eb2); zb23 = mul2(zb23, eb2);
            u64t sa01 = 0ull, sa23 = 0ull, sb01 = 0ull, sb23 = 0ull;
#pragma unroll 4
            for (int j = 0; j < BT; j++) {
                double2 ed = *(double2*)&sVE[j*VS + v0];
                u64t e01 = d2u(ed.x), e23 = d2u(ed.y);
                float ma = sM[ta*68 + j];
                float mb = sM[tb*68 + j];
                u64t ma2 = pk2(ma, ma), mb2 = pk2(mb, mb);
                sa01 = fma2(ma2, e01, sa01);
                sa23 = fma2(ma2, e23, sa23);
                sb01 = fma2(mb2, e01, sb01);
                sb23 = fma2(mb2, e23, sb23);
            }
            float z0, z1, s0, s1;
            float4 oa, ob;
            upk2(za01, z0, z1); upk2(sa01, s0, s1); oa.x = z0 - s0; oa.y = z1 - s1;
            upk2(za23, z0, z1); upk2(sa23, s0, s1); oa.z = z0 - s0; oa.w = z1 - s1;
            upk2(zb01, z0, z1); upk2(sb01, s0, s1); ob.x = z0 - s0; ob.y = z1 - s1;
            upk2(zb23, z0, z1); upk2(sb23, s0, s1); ob.z = z0 - s0; ob.w = z1 - s1;
            *(float4*)(Zp + (size_t)(t0+ta)*HD + v0) = oa;
            *(float4*)(Zp + (size_t)(t0+tb)*HD + v0) = ob;
        }
        {
#pragma unroll
            for (int i = 0; i < 4; i++) { ca01[i] = 0ull; ca23[i] = 0ull; }
#pragma unroll 2
            for (int t = 0; t < BT; t++) {
                float cf = -sCoef[t];
                u64t cf2 = pk2(cf, cf);
                double2 ed = *(double2*)&sVE[t*VS + v0];
                u64t ce01 = mul2(d2u(ed.x), cf2);
                u64t ce23 = mul2(d2u(ed.y), cf2);
                float4 k4 = *(float4*)&sK[t*132 + k0];
                u64t k20 = pk2(k4.x, k4.x), k21 = pk2(k4.y, k4.y);
                u64t k22 = pk2(k4.z, k4.z), k23 = pk2(k4.w, k4.w);
                ca01[0] = fma2(k20, ce01, ca01[0]); ca23[0] = fma2(k20, ce23, ca23[0]);
                ca01[1] = fma2(k21, ce01, ca01[1]); ca23[1] = fma2(k21, ce23, ca23[1]);
                ca01[2] = fma2(k22, ce01, ca01[2]); ca23[2] = fma2(k22, ce23, ca23[2]);
                ca01[3] = fma2(k23, ce01, ca01[3]); ca23[3] = fma2(k23, ce23, ca23[3]);
            }
        }
        __syncthreads();

        // ---- W update ----
        {
            float dk = sElec[63];
            u64t dk2 = pk2(dk, dk);
#pragma unroll
            for (int i = 0; i < 4; i++) {
                double2 wv = *(double2*)&sWt[(k0+i)*VS + v0];
                u64t w01 = fma2(d2u(wv.x), dk2, ca01[i]);
                u64t w23 = fma2(d2u(wv.y), dk2, ca23[i]);
                *(double2*)&sWt[(k0+i)*VS + v0] = make_double2(u2d(w01), u2d(w23));
            }
        }
    }
}

// ---------------- gated RMS norm -> bf16 hi/lo split ----------------
__global__ __launch_bounds__(256)
void gated_rms_split(const float* __restrict__ Zin, const float* __restrict__ G,
                     const float* __restrict__ nw, __nv_bfloat16* __restrict__ hi,
                     __nv_bfloat16* __restrict__ lo)
{
    const int gw   = blockIdx.x * 8 + (threadIdx.x >> 5);
    const int lane = threadIdx.x & 31;
    const size_t base = (size_t)gw * 128;
    float4 zv = *(const float4*)(Zin + base + lane*4);
    float ss = zv.x*zv.x + zv.y*zv.y + zv.z*zv.z + zv.w*zv.w;
#pragma unroll
    for (int o = 16; o; o >>= 1) ss += __shfl_xor_sync(0xffffffffu, ss, o);
    float r = rsqrtf(ss * (1.f/128.f) + 1e-5f);
    float4 gv = *(const float4*)(G  + base + lane*4);
    float4 wv = *(const float4*)(nw + lane*4);
    float ov[4];
    ov[0] = zv.x*r*wv.x * (gv.x / (1.f + expf(-gv.x)));
    ov[1] = zv.y*r*wv.y * (gv.y / (1.f + expf(-gv.y)));
    ov[2] = zv.z*r*wv.z * (gv.z / (1.f + expf(-gv.z)));
    ov[3] = zv.w*r*wv.w * (gv.w / (1.f + expf(-gv.w)));
    __align__(8) __nv_bfloat16 h[4], l[4];
#pragma unroll
    for (int j = 0; j < 4; j++) {
        h[j] = __float2bfloat16(ov[j]);
        l[j] = __float2bfloat16(ov[j] - __bfloat162float(h[j]));
    }
    *(uint2*)(hi + base + lane*4) = *(uint2*)h;
    *(uint2*)(lo + base + lane*4) = *(uint2*)l;
}

// ---------------- launch ----------------
extern "C" void kernel_launch(void* const* d_in, const int* in_sizes, int n_in,
                              void* d_out, int out_size)
{
    const float* X    = (const float*)d_in[0];
    const float* Wq   = (const float*)d_in[1];
    const float* Wk   = (const float*)d_in[2];
    const float* Wv   = (const float*)d_in[3];
    const float* Weta = (const float*)d_in[4];
    const float* Wth  = (const float*)d_in[5];
    const float* Wg   = (const float*)d_in[6];
    const float* nw   = (const float*)d_in[7];
    const float* Wo   = (const float*)d_in[8];
    float* out = (float*)d_out;

    float *q, *k, *v, *g, *z, *eta, *th, *lec, *elec, *coef, *Mbuf;
    __nv_bfloat16 *xhi, *xlo, *whi, *wlo, *oghi, *oglo;
    cudaGetSymbolAddress((void**)&q,    g_q);
    cudaGetSymbolAddress((void**)&k,    g_k);
    cudaGetSymbolAddress((void**)&v,    g_v);
    cudaGetSymbolAddress((void**)&g,    g_g);
    cudaGetSymbolAddress((void**)&z,    g_z);
    cudaGetSymbolAddress((void**)&eta,  g_eta);
    cudaGetSymbolAddress((void**)&th,   g_theta);
    cudaGetSymbolAddress((void**)&lec,  g_lec);
    cudaGetSymbolAddress((void**)&elec, g_elec);
    cudaGetSymbolAddress((void**)&coef, g_coef);
    cudaGetSymbolAddress((void**)&Mbuf, g_M);
    cudaGetSymbolAddress((void**)&xhi,  g_xhi);
    cudaGetSymbolAddress((void**)&xlo,  g_xlo);
    cudaGetSymbolAddress((void**)&whi,  g_whi);
    cudaGetSymbolAddress((void**)&wlo,  g_wlo);
    cudaGetSymbolAddress((void**)&oghi, g_oghi);
    cudaGetSymbolAddress((void**)&oglo, g_oglo);

    const int scan_smem = (128*VS + 64*132 + 64*132 + 64*VS + 64*68 + 2*64) * 4;
    cudaFuncSetAttribute(scan_kernel, cudaFuncAttributeMaxDynamicSharedMemorySize, scan_smem);
    const int qkm_smem = (64*132 + 64*KST + 2*64) * 4;
    cudaFuncSetAttribute(qkm_kernel, cudaFuncAttributeMaxDynamicSharedMemorySize, qkm_smem);
    const int gemm_smem = NSTG * STG_BYTES;   // 153600
    cudaFuncSetAttribute(gemm3_bf16, cudaFuncAttributeMaxDynamicSharedMemorySize, gemm_smem);

    const int WN = Dd * Dd;

    split_bf16_kernel<<<TOKS*Dd/4/256, 256>>>(X,  xhi, xlo, TOKS*Dd/4);
    split_bf16_kernel<<<WN/4/256, 256>>>(Wq, whi + 0*(size_t)WN, wlo + 0*(size_t)WN, WN/4);
    split_bf16_kernel<<<WN/4/256, 256>>>(Wk, whi + 1*(size_t)WN, wlo + 1*(size_t)WN, WN/4);
    split_bf16_kernel<<<WN/4/256, 256>>>(Wv, whi + 2*(size_t)WN, wlo + 2*(size_t)WN, WN/4);
    split_bf16_kernel<<<WN/4/256, 256>>>(Wg, whi + 3*(size_t)WN, wlo + 3*(size_t)WN, WN/4);
    split_bf16_kernel<<<WN/4/256, 256>>>(Wo, whi + 4*(size_t)WN, wlo + 4*(size_t)WN, WN/4);

    dim3 gg(HD/256, TOKS/128);   // (8, 64)
    const float qscale = 0.08838834764831845f;  // 128^-0.5

    eta_theta_kernel<<<TOKS, 256>>>(X, Weta, Wth, eta, th);
    decay_prep_kernel<<<2048/8, 256>>>(eta, th, lec, elec, coef);

    gemm3_bf16<<<gg, 256, gemm_smem>>>(xhi, xlo, whi + 0*(size_t)WN, wlo + 0*(size_t)WN, q, qscale);
    gemm3_bf16<<<gg, 256, gemm_smem>>>(xhi, xlo, whi + 1*(size_t)WN, wlo + 1*(size_t)WN, k, 1.f);
    qkm_kernel<<<32*NT, 256, qkm_smem>>>(q, k, lec, th, Mbuf);
    gemm3_bf16<<<gg, 256, gemm_smem>>>(xhi, xlo, whi + 2*(size_t)WN, wlo + 2*(size_t)WN, v, 1.f);

    scan_kernel<<<dim3(Bb*Hh, NVS), 256, scan_smem>>>(q, k, v, elec, coef, Mbuf, z);

    gemm3_bf16<<<gg, 256, gemm_smem>>>(xhi, xlo, whi + 3*(size_t)WN, wlo + 3*(size_t)WN, g, 1.f);
    gated_rms_split<<<TOKS*Hh/8, 256>>>(z, g, nw, oghi, oglo);
    gemm3_bf16<<<gg, 256, gemm_smem>>>(oghi, oglo, whi + 4*(size_t)WN, wlo + 4*(size_t)WN, out, 1.f);
}

// round 7
// speedup vs baseline: 1.4188x; 1.4188x over previous
#include <cuda_runtime.h>
#include <cuda_bf16.h>
#include <math.h>
#include <cstdint>

// Problem constants (fixed shapes)
#define Bb 2
#define Tt 4096
#define Dd 2048
#define Hh 16
#define Kk 128
#define Vv 128
#define BT 64
#define NT 64
#define TOKS (Bb*Tt)          // 8192
#define HD   (Hh*Kk)          // 2048
#define VS   32               // v-slice width in scan
#define NVS  (Vv/VS)          // 4

// ---------------- scratch (device globals; no runtime alloc) ----------------
__device__ float g_q [TOKS*HD];
__device__ float g_k [TOKS*HD];
__device__ float g_v [TOKS*HD];
__device__ float g_g [TOKS*HD];
__device__ float g_z [TOKS*HD];
__device__ float g_eta  [TOKS*Hh];
__device__ float g_theta[TOKS*Hh];
__device__ float g_lec  [32*Tt];
__device__ float g_elec [32*Tt];
__device__ float g_coef [32*Tt];
__device__ float g_M    [32*NT*BT*BT];
__device__ __nv_bfloat16 g_xhi[TOKS*Dd];
__device__ __nv_bfloat16 g_xlo[TOKS*Dd];
__device__ __nv_bfloat16 g_whi[5*Dd*Dd];
__device__ __nv_bfloat16 g_wlo[5*Dd*Dd];
__device__ __nv_bfloat16 g_oghi[TOKS*HD];
__device__ __nv_bfloat16 g_oglo[TOKS*HD];

// ---------------- helpers ----------------
typedef unsigned long long u64t;

__device__ __forceinline__ uint32_t smem_u32(const void* p) {
    uint32_t a;
    asm("{ .reg .u64 t; cvta.to.shared.u64 t, %1; cvt.u32.u64 %0, t; }" : "=r"(a) : "l"(p));
    return a;
}
__device__ __forceinline__ void ldm_x4(uint32_t (&r)[4], uint32_t addr) {
    asm volatile("ldmatrix.sync.aligned.m8n8.x4.shared.b16 {%0,%1,%2,%3}, [%4];"
                 : "=r"(r[0]), "=r"(r[1]), "=r"(r[2]), "=r"(r[3]) : "r"(addr));
}
__device__ __forceinline__ void mma16816(float (&d)[4], const uint32_t (&a)[4],
                                         uint32_t b0, uint32_t b1) {
    asm volatile(
        "mma.sync.aligned.m16n8k16.row.col.f32.bf16.bf16.f32 "
        "{%0,%1,%2,%3}, {%4,%5,%6,%7}, {%8,%9}, {%0,%1,%2,%3};"
        : "+f"(d[0]), "+f"(d[1]), "+f"(d[2]), "+f"(d[3])
        : "r"(a[0]), "r"(a[1]), "r"(a[2]), "r"(a[3]), "r"(b0), "r"(b1));
}
// packed f32x2 (FFMA2 path)
__device__ __forceinline__ u64t pk2(float lo, float hi) {
    u64t d; asm("mov.b64 %0, {%1,%2};" : "=l"(d) : "f"(lo), "f"(hi)); return d;
}
__device__ __forceinline__ void upk2(u64t s, float& lo, float& hi) {
    asm("mov.b64 {%0,%1}, %2;" : "=f"(lo), "=f"(hi) : "l"(s));
}
__device__ __forceinline__ u64t fma2(u64t a, u64t b, u64t c) {
    u64t d; asm("fma.rn.f32x2 %0, %1, %2, %3;" : "=l"(d) : "l"(a), "l"(b), "l"(c)); return d;
}
__device__ __forceinline__ u64t mul2(u64t a, u64t b) {
    u64t d; asm("mul.rn.f32x2 %0, %1, %2;" : "=l"(d) : "l"(a), "l"(b)); return d;
}
__device__ __forceinline__ u64t d2u(double x) { return __double_as_longlong(x); }
__device__ __forceinline__ double u2d(u64t x) { return __longlong_as_double(x); }

// ---------------- fp32 -> (hi,lo) bf16 split ----------------
__global__ __launch_bounds__(256)
void split_bf16_kernel(const float* __restrict__ x, __nv_bfloat16* __restrict__ hi,
                       __nv_bfloat16* __restrict__ lo, int n4)
{
    int i = blockIdx.x * 256 + threadIdx.x;
    if (i >= n4) return;
    float4 v = ((const float4*)x)[i];
    float vv[4] = {v.x, v.y, v.z, v.w};
    __align__(8) __nv_bfloat16 h[4], l[4];
#pragma unroll
    for (int j = 0; j < 4; j++) {
        h[j] = __float2bfloat16(vv[j]);
        l[j] = __float2bfloat16(vv[j] - __bfloat162float(h[j]));
    }
    ((uint2*)hi)[i] = *(uint2*)h;
    ((uint2*)lo)[i] = *(uint2*)l;
}

// ---------------- HMMA 3xBF16 GEMM: C[8192,2048] = alpha * A @ B^T ----------------
// R5 config: CTA tile 128x128, BK=32, 4-stage cp.async, 4 warps (2Mx2N), warp 64x64.
#define BKT 32
#define NKT 192                 // 3 * (2048/32)
#define ROWB 80                 // smem row stride (32 bf16 + 8 pad)
#define STG_BYTES (128*ROWB*2)  // 20480
#define NSTG 4

__device__ __forceinline__ void ld_stage(uint32_t sA, uint32_t sB,
    const __nv_bfloat16* __restrict__ A, const __nv_bfloat16* __restrict__ B,
    int bm, int bn, int k0, int tid)
{
#pragma unroll
    for (int i = 0; i < 4; i++) {
        int idx = tid + i * 128;      // 0..511
        int row = idx >> 2, c = idx & 3;
        uint32_t dA = sA + row * ROWB + c * 16;
        const void* pA = A + (size_t)(bm + row) * 2048 + k0 + c * 8;
        asm volatile("cp.async.cg.shared.global [%0], [%1], 16;" :: "r"(dA), "l"(pA) : "memory");
        uint32_t dB = sB + row * ROWB + c * 16;
        const void* pB = B + (size_t)(bn + row) * 2048 + k0 + c * 8;
        asm volatile("cp.async.cg.shared.global [%0], [%1], 16;" :: "r"(dB), "l"(pB) : "memory");
    }
}

__global__ __launch_bounds__(128, 2)
void gemm3_bf16(const __nv_bfloat16* __restrict__ Ahi, const __nv_bfloat16* __restrict__ Alo,
                const __nv_bfloat16* __restrict__ Bhi, const __nv_bfloat16* __restrict__ Blo,
                float* __restrict__ C, float alpha)
{
    extern __shared__ __align__(128) char dyn[];
    const int tid  = threadIdx.x;
    const int wid  = tid >> 5;
    const int lane = tid & 31;
    const int bm = blockIdx.y * 128;
    const int bn = blockIdx.x * 128;
    const uint32_t dynb = smem_u32(dyn);

    const int wm0 = (wid >> 1) * 64;        // 2 warps in M
    const int wn0 = (wid & 1) * 64;         // 2 warps in N

    const int q = lane >> 3, l8 = lane & 7;
    const uint32_t aoff = (uint32_t)((l8 + (q & 1) * 8) * ROWB + (q >> 1) * 16);
    const uint32_t boff = (uint32_t)((l8 + (q >> 1) * 8) * ROWB + (q & 1) * 16);

    float acc[4][8][4];
#pragma unroll
    for (int mf = 0; mf < 4; mf++)
#pragma unroll
        for (int nf = 0; nf < 8; nf++)
#pragma unroll
            for (int j = 0; j < 4; j++) acc[mf][nf][j] = 0.f;

    // prologue: stages 0..2
#pragma unroll
    for (int s = 0; s < 3; s++) {
        uint32_t base = dynb + s * STG_BYTES;
        ld_stage(base, base + 128 * ROWB, Ahi, Bhi, bm, bn, s * BKT, tid);
        asm volatile("cp.async.commit_group;" ::: "memory");
    }

    for (int kt = 0; kt < NKT; kt++) {
        asm volatile("cp.async.wait_group 2;" ::: "memory");
        __syncthreads();   // also guarantees compute(kt-1) finished before its buffer refill

        {
            int ktn = kt + 3;
            if (ktn < NKT) {
                int seg = ktn >> 6;
                int k0  = (ktn & 63) * BKT;
                const __nv_bfloat16* As_ = (seg < 2) ? Ahi : Alo;
                const __nv_bfloat16* Bs_ = (seg == 1) ? Blo : Bhi;
                uint32_t base = dynb + (ktn & 3) * STG_BYTES;
                ld_stage(base, base + 128 * ROWB, As_, Bs_, bm, bn, k0, tid);
            }
            asm volatile("cp.async.commit_group;" ::: "memory");
        }

        const uint32_t sA = dynb + (kt & 3) * STG_BYTES;
        const uint32_t sB = sA + 128 * ROWB;
#pragma unroll
        for (int ks = 0; ks < 2; ks++) {
            uint32_t a[4][4];
#pragma unroll
            for (int mf = 0; mf < 4; mf++)
                ldm_x4(a[mf], sA + (uint32_t)(wm0 + mf * 16) * ROWB + ks * 32 + aoff);
            uint32_t b[4][4];
#pragma unroll
            for (int p = 0; p < 4; p++)
                ldm_x4(b[p], sB + (uint32_t)(wn0 + p * 16) * ROWB + ks * 32 + boff);
#pragma unroll
            for (int mf = 0; mf < 4; mf++)
#pragma unroll
                for (int p = 0; p < 4; p++) {
                    mma16816(acc[mf][2*p],   a[mf], b[p][0], b[p][1]);
                    mma16816(acc[mf][2*p+1], a[mf], b[p][2], b[p][3]);
                }
        }
    }

    const int r0 = lane >> 2, c0 = (lane & 3) * 2;
#pragma unroll
    for (int mf = 0; mf < 4; mf++) {
        int rowa = bm + wm0 + mf * 16 + r0;
#pragma unroll
        for (int nf = 0; nf < 8; nf++) {
            int col = bn + wn0 + nf * 8 + c0;
            float2 v0 = {alpha * acc[mf][nf][0], alpha * acc[mf][nf][1]};
            float2 v1 = {alpha * acc[mf][nf][2], alpha * acc[mf][nf][3]};
            *(float2*)(C + (size_t)rowa * 2048 + col)       = v0;
            *(float2*)(C + (size_t)(rowa + 8) * 2048 + col) = v1;
        }
    }
}

// ---------------- eta / theta: sigmoid projections (N=16 each) ----------------
__global__ __launch_bounds__(256)
void eta_theta_kernel(const float* __restrict__ X, const float* __restrict__ Weta,
                      const float* __restrict__ Wth, float* __restrict__ Eta,
                      float* __restrict__ Th)
{
    __shared__ float sx[Dd];
    const int tok = blockIdx.x, tid = threadIdx.x;
    for (int i = tid; i < Dd/4; i += 256)
        *(float4*)&sx[i*4] = *(const float4*)(X + (size_t)tok*Dd + i*4);
    __syncthreads();
    const int p  = tid >> 3;
    const int l8 = tid & 7;
    const int h = p & 15, which = p >> 4;
    const float* w = (which ? Wth : Weta) + (size_t)h * Dd;
    float s = 0.f;
    for (int i = l8*4; i < Dd; i += 32) {
        float4 xv = *(float4*)&sx[i];
        float4 wv = *(const float4*)(w + i);
        s += xv.x*wv.x + xv.y*wv.y + xv.z*wv.z + xv.w*wv.w;
    }
    s += __shfl_xor_sync(0xffffffffu, s, 4);
    s += __shfl_xor_sync(0xffffffffu, s, 2);
    s += __shfl_xor_sync(0xffffffffu, s, 1);
    if (l8 == 0) {
        float sig = 1.f / (1.f + expf(-s));
        if (which) Th[(size_t)tok*Hh + h] = 0.1f * sig;
        else       Eta[(size_t)tok*Hh + h] = sig;
    }
}

// ---------------- decay prep ----------------
__global__ __launch_bounds__(256)
void decay_prep_kernel(const float* __restrict__ Eta, const float* __restrict__ Th,
                       float* __restrict__ Lec, float* __restrict__ Elec,
                       float* __restrict__ Coef)
{
    const int wc   = blockIdx.x * 8 + (threadIdx.x >> 5);   // bh*64+ct
    const int lane = threadIdx.x & 31;
    const int bh = wc >> 6, ct = wc & 63;
    const int b = bh >> 4, h = bh & 15;
    const size_t tokbase = (size_t)b * Tt;
    const int t = ct * BT + lane * 2;
    float e0  = Eta[(tokbase + t) * Hh + h];
    float e1  = Eta[(tokbase + t + 1) * Hh + h];
    float th0 = Th [(tokbase + t) * Hh + h];
    float th1 = Th [(tokbase + t + 1) * Hh + h];
    float l0 = logf(fmaxf(e0, 1e-8f));
    float l1 = logf(fmaxf(e1, 1e-8f));
    float s = l0 + l1;
#pragma unroll
    for (int o = 1; o < 32; o <<= 1) {
        float n = __shfl_up_sync(0xffffffffu, s, o);
        if (lane >= o) s += n;
    }
    float lec1 = s;
    float lec0 = s - l1;
    float ltot = __shfl_sync(0xffffffffu, s, 31);
    size_t base = (size_t)bh * Tt + t;
    float2 lv = {lec0, lec1};
    float2 ev = {expf(lec0), expf(lec1)};
    float2 cv = {expf(ltot - lec0) * th0, expf(ltot - lec1) * th1};
    *(float2*)(Lec  + base) = lv;
    *(float2*)(Elec + base) = ev;
    *(float2*)(Coef + base) = cv;
}

// ---------------- qkm: M[i][j] = (q_i.k_j)*beta(i,j)*theta_j, row-major (no transpose) ----------------
#define KST 130   // sK row stride (floats); 2-way worst-case conflicts
__global__ __launch_bounds__(256)
void qkm_kernel(const float* __restrict__ Q, const float* __restrict__ Kc,
                const float* __restrict__ Lec, const float* __restrict__ Th,
                float* __restrict__ Mout)
{
    extern __shared__ float qsm[];
    float* sQ   = qsm;            // 64*132
    float* sK   = sQ + 64*132;    // 64*130
    float* sLec = sK + 64*KST;    // 64
    float* sTh  = sLec + 64;      // 64

    const int blk = blockIdx.x;   // bh*64+ct
    const int bh = blk >> 6, ct = blk & 63;
    const int b = bh >> 4, h = bh & 15;
    const int tid = threadIdx.x;
    const size_t tokbase = (size_t)b * Tt;
    const int t0 = ct * BT;
    const float* Qp = Q  + tokbase*HD + (size_t)h*Kk;
    const float* Kp = Kc + tokbase*HD + (size_t)h*Kk;

#pragma unroll
    for (int i = 0; i < 8; i++) {
        int idx = tid + i*256;
        int r = idx >> 5, c = (idx & 31) << 2;
        float4 qv = *(const float4*)(Qp + (size_t)(t0+r)*HD + c);
        *(float4*)&sQ[r*132 + c] = qv;
        float4 kv = *(const float4*)(Kp + (size_t)(t0+r)*HD + c);
        float2 k01 = {kv.x, kv.y}, k23 = {kv.z, kv.w};
        *(float2*)&sK[r*KST + c]     = k01;
        *(float2*)&sK[r*KST + c + 2] = k23;
    }
    if (tid < 64) {
        sLec[tid] = Lec[(size_t)bh * Tt + t0 + tid];
        sTh[tid]  = Th[(tokbase + t0 + tid) * Hh + h];
    }
    __syncthreads();

    const int tx = tid & 15, ty = tid >> 4;
    const int i0 = ty*4;                     // 4 consecutive i rows
    float acc[4][4];                         // [i][s], j = tx + 16*s
#pragma unroll
    for (int i = 0; i < 4; i++)
#pragma unroll
        for (int s = 0; s < 4; s++) acc[i][s] = 0.f;
#pragma unroll 4
    for (int kk = 0; kk < Kk; kk++) {
        float kj[4], qi[4];
#pragma unroll
        for (int s = 0; s < 4; s++) kj[s] = sK[(tx + 16*s)*KST + kk];
#pragma unroll
        for (int i = 0; i < 4; i++) qi[i] = sQ[(i0+i)*132 + kk];
#pragma unroll
        for (int i = 0; i < 4; i++)
#pragma unroll
            for (int s = 0; s < 4; s++) acc[i][s] += qi[i] * kj[s];
    }
    float* Mo = Mout + (size_t)blk * (BT*BT);
#pragma unroll
    for (int i = 0; i < 4; i++) {
        int ii = i0 + i;
        float li = sLec[ii];
#pragma unroll
        for (int s = 0; s < 4; s++) {
            int jj = tx + 16*s;
            float m = 0.f;
            if (jj <= ii)
                m = acc[i][s] * expf(fminf(li - sLec[jj], 0.f)) * sTh[jj];
            Mo[ii*64 + jj] = m;
        }
    }
}

// ---------------- chunked fast-weight scan: fused kW/qW pass, f32x2 ----------------
__global__ __launch_bounds__(256, 1)
void scan_kernel(const float* __restrict__ Q, const float* __restrict__ Kc,
                 const float* __restrict__ Vc, const float* __restrict__ Elec,
                 const float* __restrict__ Coef, const float* __restrict__ Mg,
                 float* __restrict__ Z)
{
    extern __shared__ float sm[];
    float* sWt   = sm;                    // [128][32]  W^T slice
    float* sQ    = sWt  + 128*VS;         // [64][132]
    float* sK    = sQ   + 64*132;         // [64][132]
    float* sVE   = sK   + 64*132;         // [64][32]
    float* sM    = sVE  + 64*VS;          // [64][68]
    float* sElec = sM   + 64*68;          // [64]
    float* sCoef = sElec + 64;            // [64]

    const int tid = threadIdx.x;
    const int bh  = blockIdx.x;
    const int b = bh >> 4, h = bh & 15;
    const int vs0 = blockIdx.y * VS;

    const size_t tokbase = (size_t)b * Tt;
    const float* Qp = Q  + tokbase*HD + (size_t)h*Kk;
    const float* Kp = Kc + tokbase*HD + (size_t)h*Kk;
    const float* Vp = Vc + tokbase*HD + (size_t)h*Vv + vs0;
    const float* Mp = Mg + (size_t)bh * (NT*BT*BT);
    float*       Zp = Z  + tokbase*HD + (size_t)h*Vv + vs0;

    for (int i = tid; i < 128*VS; i += 256) sWt[i] = 0.f;

    const int tx = tid & 7;               // v quad
    const int ty = tid >> 3;              // 0..31
    const int v0 = tx << 2;
    const int ta = ty*2, tb = ta + 1;     // row pair
    const int k0 = ty << 2;               // 4 k-rows for W update

    for (int ct = 0; ct < NT; ct++) {
        const int t0 = ct * BT;
        __syncthreads();

        // ---- loads ----
#pragma unroll
        for (int i = 0; i < 8; i++) {
            int idx = tid + i*256;
            int r = idx >> 5;
            int c = (idx & 31) << 2;
            *(float4*)&sQ[r*132 + c] = *(const float4*)(Qp + (size_t)(t0+r)*HD + c);
            *(float4*)&sK[r*132 + c] = *(const float4*)(Kp + (size_t)(t0+r)*HD + c);
        }
#pragma unroll
        for (int i = 0; i < 2; i++) {
            int idx = tid + i*256;
            int r = idx >> 3;
            int c = (idx & 7) << 2;
            *(float4*)&sVE[r*VS + c] = *(const float4*)(Vp + (size_t)(t0+r)*HD + c);
        }
#pragma unroll
        for (int i = 0; i < 4; i++) {
            int idx = tid + i*256;
            int r = idx >> 4;
            int c = (idx & 15) << 2;
            *(float4*)&sM[r*68 + c] = *(const float4*)(Mp + ct*(BT*BT) + r*64 + c);
        }
        if (tid < 64) {
            sElec[tid] = Elec[(size_t)bh*Tt + t0 + tid];
            sCoef[tid] = Coef[(size_t)bh*Tt + t0 + tid];
        }
        __syncthreads();

        // ---- Phase A: e = k@W^T - v  AND  zq = q@W^T (single W pass) ----
        u64t za01, za23, zb01, zb23;
        {
            float4 va = *(float4*)&sVE[ta*VS + v0];
            float4 vb = *(float4*)&sVE[tb*VS + v0];
            u64t ea01 = pk2(-va.x, -va.y), ea23 = pk2(-va.z, -va.w);
            u64t eb01 = pk2(-vb.x, -vb.y), eb23 = pk2(-vb.z, -vb.w);
            za01 = 0ull; za23 = 0ull; zb01 = 0ull; zb23 = 0ull;
#pragma unroll 4
            for (int kk = 0; kk < Kk; kk++) {
                double2 wd = *(double2*)&sWt[kk*VS + v0];
                u64t w01 = d2u(wd.x), w23 = d2u(wd.y);
                float ka = sK[ta*132 + kk];
                float kb = sK[tb*132 + kk];
                float qa = sQ[ta*132 + kk];
                float qb = sQ[tb*132 + kk];
                u64t ka2 = pk2(ka, ka), kb2 = pk2(kb, kb);
                u64t qa2 = pk2(qa, qa), qb2 = pk2(qb, qb);
                ea01 = fma2(ka2, w01, ea01);
                ea23 = fma2(ka2, w23, ea23);
                eb01 = fma2(kb2, w01, eb01);
                eb23 = fma2(kb2, w23, eb23);
                za01 = fma2(qa2, w01, za01);
                za23 = fma2(qa2, w23, za23);
                zb01 = fma2(qb2, w01, zb01);
                zb23 = fma2(qb2, w23, zb23);
            }
            *(double2*)&sVE[ta*VS + v0] = make_double2(u2d(ea01), u2d(ea23));
            *(double2*)&sVE[tb*VS + v0] = make_double2(u2d(eb01), u2d(eb23));
        }
        __syncthreads();

        // ---- Phase B: z = elec*zq - M@e ; Phase C accum ----
        u64t ca01[4], ca23[4];
        {
            float ea = sElec[ta], eb = sElec[tb];
            u64t ea2 = pk2(ea, ea), eb2 = pk2(eb, eb);
            za01 = mul2(za01, ea2); za23 = mul2(za23, ea2);
            zb01 = mul2(zb01, eb2); zb23 = mul2(zb23, eb2);
            u64t sa01 = 0ull, sa23 = 0ull, sb01 = 0ull, sb23 = 0ull;
#pragma unroll 4
            for (int j = 0; j < BT; j++) {
                double2 ed = *(double2*)&sVE[j*VS + v0];
                u64t e01 = d2u(ed.x), e23 = d2u(ed.y);
                float ma = sM[ta*68 + j];
                float mb = sM[tb*68 + j];
                u64t ma2 = pk2(ma, ma), mb2 = pk2(mb, mb);
                sa01 = fma2(ma2, e01, sa01);
                sa23 = fma2(ma2, e23, sa23);
                sb01 = fma2(mb2, e01, sb01);
                sb23 = fma2(mb2, e23, sb23);
            }
            float z0, z1, s0, s1;
            float4 oa, ob;
            upk2(za01, z0, z1); upk2(sa01, s0, s1); oa.x = z0 - s0; oa.y = z1 - s1;
            upk2(za23, z0, z1); upk2(sa23, s0, s1); oa.z = z0 - s0; oa.w = z1 - s1;
            upk2(zb01, z0, z1); upk2(sb01, s0, s1); ob.x = z0 - s0; ob.y = z1 - s1;
            upk2(zb23, z0, z1); upk2(sb23, s0, s1); ob.z = z0 - s0; ob.w = z1 - s1;
            *(float4*)(Zp + (size_t)(t0+ta)*HD + v0) = oa;
            *(float4*)(Zp + (size_t)(t0+tb)*HD + v0) = ob;
        }
        {
#pragma unroll
            for (int i = 0; i < 4; i++) { ca01[i] = 0ull; ca23[i] = 0ull; }
#pragma unroll 2
            for (int t = 0; t < BT; t++) {
                float cf = -sCoef[t];
                u64t cf2 = pk2(cf, cf);
                double2 ed = *(double2*)&sVE[t*VS + v0];
                u64t ce01 = mul2(d2u(ed.x), cf2);
                u64t ce23 = mul2(d2u(ed.y), cf2);
                float4 k4 = *(float4*)&sK[t*132 + k0];
                u64t k20 = pk2(k4.x, k4.x), k21 = pk2(k4.y, k4.y);
                u64t k22 = pk2(k4.z, k4.z), k23 = pk2(k4.w, k4.w);
                ca01[0] = fma2(k20, ce01, ca01[0]); ca23[0] = fma2(k20, ce23, ca23[0]);
                ca01[1] = fma2(k21, ce01, ca01[1]); ca23[1] = fma2(k21, ce23, ca23[1]);
                ca01[2] = fma2(k22, ce01, ca01[2]); ca23[2] = fma2(k22, ce23, ca23[2]);
                ca01[3] = fma2(k23, ce01, ca01[3]); ca23[3] = fma2(k23, ce23, ca23[3]);
            }
        }
        __syncthreads();

        // ---- W update ----
        {
            float dk = sElec[63];
            u64t dk2 = pk2(dk, dk);
#pragma unroll
            for (int i = 0; i < 4; i++) {
                double2 wv = *(double2*)&sWt[(k0+i)*VS + v0];
                u64t w01 = fma2(d2u(wv.x), dk2, ca01[i]);
                u64t w23 = fma2(d2u(wv.y), dk2, ca23[i]);
                *(double2*)&sWt[(k0+i)*VS + v0] = make_double2(u2d(w01), u2d(w23));
            }
        }
    }
}

// ---------------- gated RMS norm -> bf16 hi/lo split ----------------
__global__ __launch_bounds__(256)
void gated_rms_split(const float* __restrict__ Zin, const float* __restrict__ G,
                     const float* __restrict__ nw, __nv_bfloat16* __restrict__ hi,
                     __nv_bfloat16* __restrict__ lo)
{
    const int gw   = blockIdx.x * 8 + (threadIdx.x >> 5);
    const int lane = threadIdx.x & 31;
    const size_t base = (size_t)gw * 128;
    float4 zv = *(const float4*)(Zin + base + lane*4);
    float ss = zv.x*zv.x + zv.y*zv.y + zv.z*zv.z + zv.w*zv.w;
#pragma unroll
    for (int o = 16; o; o >>= 1) ss += __shfl_xor_sync(0xffffffffu, ss, o);
    float r = rsqrtf(ss * (1.f/128.f) + 1e-5f);
    float4 gv = *(const float4*)(G  + base + lane*4);
    float4 wv = *(const float4*)(nw + lane*4);
    float ov[4];
    ov[0] = zv.x*r*wv.x * (gv.x / (1.f + expf(-gv.x)));
    ov[1] = zv.y*r*wv.y * (gv.y / (1.f + expf(-gv.y)));
    ov[2] = zv.z*r*wv.z * (gv.z / (1.f + expf(-gv.z)));
    ov[3] = zv.w*r*wv.w * (gv.w / (1.f + expf(-gv.w)));
    __align__(8) __nv_bfloat16 h[4], l[4];
#pragma unroll
    for (int j = 0; j < 4; j++) {
        h[j] = __float2bfloat16(ov[j]);
        l[j] = __float2bfloat16(ov[j] - __bfloat162float(h[j]));
    }
    *(uint2*)(hi + base + lane*4) = *(uint2*)h;
    *(uint2*)(lo + base + lane*4) = *(uint2*)l;
}

// ---------------- launch ----------------
extern "C" void kernel_launch(void* const* d_in, const int* in_sizes, int n_in,
                              void* d_out, int out_size)
{
    const float* X    = (const float*)d_in[0];
    const float* Wq   = (const float*)d_in[1];
    const float* Wk   = (const float*)d_in[2];
    const float* Wv   = (const float*)d_in[3];
    const float* Weta = (const float*)d_in[4];
    const float* Wth  = (const float*)d_in[5];
    const float* Wg   = (const float*)d_in[6];
    const float* nw   = (const float*)d_in[7];
    const float* Wo   = (const float*)d_in[8];
    float* out = (float*)d_out;

    float *q, *k, *v, *g, *z, *eta, *th, *lec, *elec, *coef, *Mbuf;
    __nv_bfloat16 *xhi, *xlo, *whi, *wlo, *oghi, *oglo;
    cudaGetSymbolAddress((void**)&q,    g_q);
    cudaGetSymbolAddress((void**)&k,    g_k);
    cudaGetSymbolAddress((void**)&v,    g_v);
    cudaGetSymbolAddress((void**)&g,    g_g);
    cudaGetSymbolAddress((void**)&z,    g_z);
    cudaGetSymbolAddress((void**)&eta,  g_eta);
    cudaGetSymbolAddress((void**)&th,   g_theta);
    cudaGetSymbolAddress((void**)&lec,  g_lec);
    cudaGetSymbolAddress((void**)&elec, g_elec);
    cudaGetSymbolAddress((void**)&coef, g_coef);
    cudaGetSymbolAddress((void**)&Mbuf, g_M);
    cudaGetSymbolAddress((void**)&xhi,  g_xhi);
    cudaGetSymbolAddress((void**)&xlo,  g_xlo);
    cudaGetSymbolAddress((void**)&whi,  g_whi);
    cudaGetSymbolAddress((void**)&wlo,  g_wlo);
    cudaGetSymbolAddress((void**)&oghi, g_oghi);
    cudaGetSymbolAddress((void**)&oglo, g_oglo);

    const int scan_smem = (128*VS + 64*132 + 64*132 + 64*VS + 64*68 + 2*64) * 4;
    cudaFuncSetAttribute(scan_kernel, cudaFuncAttributeMaxDynamicSharedMemorySize, scan_smem);
    const int qkm_smem = (64*132 + 64*KST + 2*64) * 4;
    cudaFuncSetAttribute(qkm_kernel, cudaFuncAttributeMaxDynamicSharedMemorySize, qkm_smem);
    const int gemm_smem = NSTG * STG_BYTES;   // 81920
    cudaFuncSetAttribute(gemm3_bf16, cudaFuncAttributeMaxDynamicSharedMemorySize, gemm_smem);

    const int WN = Dd * Dd;

    split_bf16_kernel<<<TOKS*Dd/4/256, 256>>>(X,  xhi, xlo, TOKS*Dd/4);
    split_bf16_kernel<<<WN/4/256, 256>>>(Wq, whi + 0*(size_t)WN, wlo + 0*(size_t)WN, WN/4);
    split_bf16_kernel<<<WN/4/256, 256>>>(Wk, whi + 1*(size_t)WN, wlo + 1*(size_t)WN, WN/4);
    split_bf16_kernel<<<WN/4/256, 256>>>(Wv, whi + 2*(size_t)WN, wlo + 2*(size_t)WN, WN/4);
    split_bf16_kernel<<<WN/4/256, 256>>>(Wg, whi + 3*(size_t)WN, wlo + 3*(size_t)WN, WN/4);
    split_bf16_kernel<<<WN/4/256, 256>>>(Wo, whi + 4*(size_t)WN, wlo + 4*(size_t)WN, WN/4);

    dim3 gg(HD/128, TOKS/128);   // (16, 64)
    const float qscale = 0.08838834764831845f;  // 128^-0.5

    eta_theta_kernel<<<TOKS, 256>>>(X, Weta, Wth, eta, th);
    decay_prep_kernel<<<2048/8, 256>>>(eta, th, lec, elec, coef);

    gemm3_bf16<<<gg, 128, gemm_smem>>>(xhi, xlo, whi + 0*(size_t)WN, wlo + 0*(size_t)WN, q, qscale);
    gemm3_bf16<<<gg, 128, gemm_smem>>>(xhi, xlo, whi + 1*(size_t)WN, wlo + 1*(size_t)WN, k, 1.f);
    qkm_kernel<<<32*NT, 256, qkm_smem>>>(q, k, lec, th, Mbuf);
    gemm3_bf16<<<gg, 128, gemm_smem>>>(xhi, xlo, whi + 2*(size_t)WN, wlo + 2*(size_t)WN, v, 1.f);

    scan_kernel<<<dim3(Bb*Hh, NVS), 256, scan_smem>>>(q, k, v, elec, coef, Mbuf, z);

    gemm3_bf16<<<gg, 128, gemm_smem>>>(xhi, xlo, whi + 3*(size_t)WN, wlo + 3*(size_t)WN, g, 1.f);
    gated_rms_split<<<TOKS*Hh/8, 256>>>(z, g, nw, oghi, oglo);
    gemm3_bf16<<<gg, 128, gemm_smem>>>(oghi, oglo, whi + 4*(size_t)WN, wlo + 4*(size_t)WN, out, 1.f);
}